// round 16
// baseline (speedup 1.0000x reference)
#include <cuda_runtime.h>
#include <cuda_fp16.h>
#include <cstdint>

// ---------------- problem constants ----------------
#define B_SZ 512
#define D_SZ 256
#define C_SZ 100000
#define C_PAD 100352              // 392 * 256
#define NCHB 392                  // class chunks of 256
#define MARGIN 0.2f
#define SCALE  30.0f
#define SHIFT  30.0f              // fixed LSE shift: logits <= S = 30
#define WCONV_BLOCKS 6272         // 16 classes per block (2 per warp), covers C_PAD
#define SPEC_BLOCKS  256          // 2 rows per block (8 warps = 2x4 queries)
#define PREP_BLOCKS (WCONV_BLOCKS + B_SZ + SPEC_BLOCKS)

// GEMM smem: 4 stages x (A 8KB + B 16KB) = 96KB, + 2KB reduce buffer -> 2 CTAs/SM
#define STAGE_BYTES 24576
#define RBUF_OFF    98304
#define GEMM_SMEM   (98304 + 2048)

// ---------------- device scratch (no runtime alloc) ----------------
__device__ __align__(16) __half g_wh[(size_t)C_PAD * D_SZ];  // l2norm(W) fp16; pad rows zero
__device__ __align__(16) __half g_xh[B_SZ * D_SZ];           // S * l2norm(x) fp16
__device__ float g_rowsum[B_SZ];                // per-row sum of exp(v - SHIFT), atomic
__device__ float g_sv[B_SZ * 4];                // post-scatter special values
__device__ float g_svraw[B_SZ * 4];             // raw S*cos at special indices (quantized ops)
__device__ int   g_sidx[B_SZ * 4];              // special indices

// ---------------- PTX helpers ----------------
__device__ __forceinline__ uint32_t smem_u32(const void* p) {
    uint32_t a;
    asm("{ .reg .u64 t; cvta.to.shared.u64 t, %1; cvt.u32.u64 %0, t; }" : "=r"(a) : "l"(p));
    return a;
}
#define CP_ASYNC16(dst, src) \
    asm volatile("cp.async.cg.shared.global [%0], [%1], 16;" :: "r"(dst), "l"(src) : "memory")
#define CP_COMMIT() asm volatile("cp.async.commit_group;" ::: "memory")
#define CP_WAIT(n)  asm volatile("cp.async.wait_group %0;" :: "n"(n) : "memory")

#define LDSM_X4(r0, r1, r2, r3, addr) \
    asm volatile("ldmatrix.sync.aligned.m8n8.x4.shared.b16 {%0,%1,%2,%3}, [%4];" \
        : "=r"(r0), "=r"(r1), "=r"(r2), "=r"(r3) : "r"(addr))

// fp16 in, fp16 accumulate: D(2x f16x2) = A(4) * B(2) + D
#define MMA_F16ACC(d0, d1, a0, a1, a2, a3, b0, b1) \
    asm volatile("mma.sync.aligned.m16n8k16.row.col.f16.f16.f16.f16 " \
        "{%0,%1}, {%2,%3,%4,%5}, {%6,%7}, {%0,%1};" \
        : "+r"(d0), "+r"(d1) \
        : "r"(a0), "r"(a1), "r"(a2), "r"(a3), "r"(b0), "r"(b1))

__device__ __forceinline__ float q16(float v) {   // quantize to fp16, back to fp32
    return __half2float(__float2half_rn(v));
}

// ---------------- kernel 1: fused prep (W conv | x conv | specials) ----------------
__global__ void prep_kernel(const float* __restrict__ w, const float* __restrict__ x,
                            const int* __restrict__ t1, const int* __restrict__ p1,
                            const int* __restrict__ t2, const int* __restrict__ p2) {
    int bid = blockIdx.x;
    if (bid < WCONV_BLOCKS) {
        // ---- W rows -> l2norm fp16, 16 classes/block, 2 per warp ----
        int cls0 = bid * 16 + (threadIdx.x >> 5) * 2;
        int lane = threadIdx.x & 31;
        if (cls0 >= C_SZ) {
            // pad rows: zero-fill so the GEMM's padded classes contribute exp(-inf)=0... 
            // (they contribute exp(0*...)=exp(-SHIFT) if left stale — must be zeroed once;
            // static __device__ arrays are zero-initialized, and we never write pad rows,
            // so nothing to do here.)
            return;
        }
        int cls1 = cls0 + 1;
        const float4* w0r = (const float4*)(w + (size_t)cls0 * D_SZ);
        const float4* w1r = (const float4*)(w + (size_t)(cls1 < C_SZ ? cls1 : cls0) * D_SZ);
        float4 a0 = w0r[lane], a1 = w0r[lane + 32];
        float4 b0 = w1r[lane], b1 = w1r[lane + 32];
        float sa = a0.x*a0.x + a0.y*a0.y + a0.z*a0.z + a0.w*a0.w
                 + a1.x*a1.x + a1.y*a1.y + a1.z*a1.z + a1.w*a1.w;
        float sb = b0.x*b0.x + b0.y*b0.y + b0.z*b0.z + b0.w*b0.w
                 + b1.x*b1.x + b1.y*b1.y + b1.z*b1.z + b1.w*b1.w;
        #pragma unroll
        for (int m = 16; m; m >>= 1) {
            sa += __shfl_xor_sync(0xffffffffu, sa, m);
            sb += __shfl_xor_sync(0xffffffffu, sb, m);
        }
        float ia = 1.0f / fmaxf(sqrtf(sa), 1e-12f);
        float ib = 1.0f / fmaxf(sqrtf(sb), 1e-12f);
        __half2* o0 = (__half2*)(g_wh + (size_t)cls0 * D_SZ);
        o0[2*lane]        = __floats2half2_rn(a0.x * ia, a0.y * ia);
        o0[2*lane + 1]    = __floats2half2_rn(a0.z * ia, a0.w * ia);
        o0[64 + 2*lane]   = __floats2half2_rn(a1.x * ia, a1.y * ia);
        o0[64 + 2*lane+1] = __floats2half2_rn(a1.z * ia, a1.w * ia);
        if (cls1 < C_SZ) {
            __half2* o1 = (__half2*)(g_wh + (size_t)cls1 * D_SZ);
            o1[2*lane]        = __floats2half2_rn(b0.x * ib, b0.y * ib);
            o1[2*lane + 1]    = __floats2half2_rn(b0.z * ib, b0.w * ib);
            o1[64 + 2*lane]   = __floats2half2_rn(b1.x * ib, b1.y * ib);
            o1[64 + 2*lane+1] = __floats2half2_rn(b1.z * ib, b1.w * ib);
        }
    } else if (bid < WCONV_BLOCKS + B_SZ) {
        // ---- x row -> S * l2norm(x) fp16 ----
        int b = bid - WCONV_BLOCKS, t = threadIdx.x;   // 256 threads
        if (t == 0) g_rowsum[b] = 0.f;                 // per-call reset (graph-replay safe)
        float v = x[b * D_SZ + t];
        float s = v * v;
        #pragma unroll
        for (int m = 16; m; m >>= 1) s += __shfl_xor_sync(0xffffffffu, s, m);
        __shared__ float ws[8];
        if ((t & 31) == 0) ws[t >> 5] = s;
        __syncthreads();
        __shared__ float inv;
        if (t == 0) {
            float tot = 0.f;
            #pragma unroll
            for (int i = 0; i < 8; i++) tot += ws[i];
            inv = 1.0f / fmaxf(sqrtf(tot), 1e-12f);
        }
        __syncthreads();
        g_xh[b * D_SZ + t] = __float2half_rn(SCALE * v * inv);
    } else {
        // ---- specials: 8 warps = 2 rows x 4 queries; inline quantization ----
        int wid = threadIdx.x >> 5, lane = threadIdx.x & 31;
        int b = (bid - (WCONV_BLOCKS + B_SZ)) * 2 + (wid >> 2);
        int q = wid & 3;
        int i0 = t1[b], i1 = p1[b], i2 = t2[b], i3 = p2[b];
        int qi = (q == 0) ? i0 : (q == 1) ? i1 : (q == 2) ? i2 : i3;

        const float4* xr = (const float4*)(x + (size_t)b * D_SZ);
        const float4* wr = (const float4*)(w + (size_t)qi * D_SZ);
        float4 x0 = xr[2*lane], x1 = xr[2*lane+1];
        float4 w0 = wr[2*lane], w1 = wr[2*lane+1];
        float sx = x0.x*x0.x + x0.y*x0.y + x0.z*x0.z + x0.w*x0.w
                 + x1.x*x1.x + x1.y*x1.y + x1.z*x1.z + x1.w*x1.w;
        float sw = w0.x*w0.x + w0.y*w0.y + w0.z*w0.z + w0.w*w0.w
                 + w1.x*w1.x + w1.y*w1.y + w1.z*w1.z + w1.w*w1.w;
        #pragma unroll
        for (int m = 16; m; m >>= 1) {
            sx += __shfl_xor_sync(0xffffffffu, sx, m);
            sw += __shfl_xor_sync(0xffffffffu, sw, m);
        }
        float ix = 1.0f / fmaxf(sqrtf(sx), 1e-12f);
        float iw = 1.0f / fmaxf(sqrtf(sw), 1e-12f);
        float xq[8] = {x0.x, x0.y, x0.z, x0.w, x1.x, x1.y, x1.z, x1.w};
        float wq[8] = {w0.x, w0.y, w0.z, w0.w, w1.x, w1.y, w1.z, w1.w};
        float s = 0.f;
        #pragma unroll
        for (int i = 0; i < 8; i++)
            s += q16(SCALE * xq[i] * ix) * q16(wq[i] * iw);
        #pragma unroll
        for (int m = 16; m; m >>= 1) s += __shfl_xor_sync(0xffffffffu, s, m);
        if (lane == 0) {
            float raw = s;                               // ~= what the GEMM sums
            float val = raw;
            if (qi == i0) val = raw - SCALE * MARGIN;    // pre-scale scatter
            if (qi == i1) val = raw / SCALE - MARGIN;    // post-scale scatters
            if (qi == i2) val = raw / SCALE - MARGIN;
            if (qi == i3) val = raw / SCALE - MARGIN;    // last write wins
            g_svraw[b * 4 + q] = raw;
            g_sv[b * 4 + q] = val;
            g_sidx[b * 4 + q] = qi;
        }
    }
}

// ---------------- kernel 2: fp16 HMMA GEMM, CTA 128x256, 8 warps of 64x64 ----------------
// grid (4, 392). 256 threads = 8 warps (2m x 4n); 2 CTAs/SM = 16 warps/SM.
__global__ void __launch_bounds__(256, 2)
gemm_lse_kernel() {
    extern __shared__ __align__(1024) char smem[];
    const uint32_t sb = smem_u32(smem);
    const int tid = threadIdx.x, lane = tid & 31, wid = tid >> 5;
    const int wm = wid >> 2, wn = wid & 3;            // warp grid 2m x 4n
    const int chunk = blockIdx.y, c0 = chunk * 256, b0 = blockIdx.x * 128;

    // ---- cp.async producer: A 512 chunks (2/thr) + B 1024 chunks (4/thr) ----
    uint32_t swzA[2], swzB[4];
    const __half *gA[2], *gB[4];
    #pragma unroll
    for (int i = 0; i < 2; i++) {
        int f = tid + 256 * i;                // 16B chunk id in 128x32 A tile
        int row = f >> 2, c16 = f & 3;
        swzA[i] = (uint32_t)row * 64 + ((uint32_t)(c16 ^ ((row >> 1) & 3)) << 4);
        gA[i] = g_xh + (size_t)(b0 + row) * D_SZ + c16 * 8;
    }
    #pragma unroll
    for (int i = 0; i < 4; i++) {
        int f = tid + 256 * i;                // 16B chunk id in 256x32 B tile
        int row = f >> 2, c16 = f & 3;
        swzB[i] = (uint32_t)row * 64 + ((uint32_t)(c16 ^ ((row >> 1) & 3)) << 4);
        gB[i] = g_wh + (size_t)(c0 + row) * D_SZ + c16 * 8;
    }

    auto load_stage = [&](int kt) {
        uint32_t abase = sb + (kt & 3) * STAGE_BYTES;
        uint32_t bbase = abase + 8192;
        #pragma unroll
        for (int i = 0; i < 2; i++) CP_ASYNC16(abase + swzA[i], gA[i] + kt * 32);
        #pragma unroll
        for (int i = 0; i < 4; i++) CP_ASYNC16(bbase + swzB[i], gB[i] + kt * 32);
        CP_COMMIT();
    };

    // ---- ldmatrix consumer indexing ----
    const int rA = wm * 64 + (lane & 15);
    const uint32_t aoff = (uint32_t)rA * 64;
    const int saN = (rA >> 1) & 3;
    const int cA = lane >> 4;
    const int rB = wn * 64 + ((lane >> 4) << 3) + (lane & 7);
    const uint32_t boff = (uint32_t)rB * 64;
    const int sbN = (rB >> 1) & 3;
    const int cB = (lane >> 3) & 1;

    uint32_t acc[4][8][2];                 // f16x2 accumulators, 64 regs
    #pragma unroll
    for (int i = 0; i < 4; i++)
        #pragma unroll
        for (int j = 0; j < 8; j++) { acc[i][j][0] = 0u; acc[i][j][1] = 0u; }

    auto compute_stage = [&](int st) {
        uint32_t aBase = sb + st * STAGE_BYTES;
        uint32_t bBase = aBase + 8192;
        #pragma unroll
        for (int s = 0; s < 2; s++) {                 // two k16 steps per BK=32
            uint32_t a_[4][4], b_[4][4];
            #pragma unroll
            for (int mt = 0; mt < 4; mt++) {
                uint32_t ad = aBase + aoff + mt * 1024 +
                              ((uint32_t)((s * 2 + cA) ^ saN) << 4);
                LDSM_X4(a_[mt][0], a_[mt][1], a_[mt][2], a_[mt][3], ad);
            }
            #pragma unroll
            for (int jp = 0; jp < 4; jp++) {
                uint32_t bd = bBase + boff + jp * 1024 +
                              ((uint32_t)((s * 2 + cB) ^ sbN) << 4);
                LDSM_X4(b_[jp][0], b_[jp][1], b_[jp][2], b_[jp][3], bd);
            }
            #pragma unroll
            for (int mt = 0; mt < 4; mt++)
                #pragma unroll
                for (int nt = 0; nt < 8; nt++) {
                    int jp = nt >> 1, hb = (nt & 1) * 2;
                    MMA_F16ACC(acc[mt][nt][0], acc[mt][nt][1],
                               a_[mt][0], a_[mt][1], a_[mt][2], a_[mt][3],
                               b_[jp][hb], b_[jp][hb + 1]);
                }
        }
    };

    // ---- pipeline: 8 K-stages, 4 buffers, 3 in flight ----
    load_stage(0); load_stage(1); load_stage(2);
    #pragma unroll 1
    for (int kt = 0; kt < 5; kt++) {
        CP_WAIT(2); __syncthreads();
        compute_stage(kt & 3);
        load_stage(kt + 3);
    }
    CP_WAIT(2); __syncthreads(); compute_stage(1);
    CP_WAIT(1); __syncthreads(); compute_stage(2);
    CP_WAIT(0); __syncthreads(); compute_stage(3);

    // ---- epilogue: per-row sum of exp(v - SHIFT), one atomic per row ----
    const bool edge = (c0 + 256 > C_SZ);
    float es[4][2];
    #pragma unroll
    for (int mt = 0; mt < 4; mt++) { es[mt][0] = 0.f; es[mt][1] = 0.f; }
    #pragma unroll
    for (int mt = 0; mt < 4; mt++)
        #pragma unroll
        for (int nt = 0; nt < 8; nt++) {
            int cgb = c0 + wn * 64 + nt * 8 + (lane & 3) * 2;
            #pragma unroll
            for (int h = 0; h < 2; h++) {
                float2 v = __half22float2(*(__half2*)&acc[mt][nt][h]);
                float t0 = __expf(v.x - SHIFT);
                float t1 = __expf(v.y - SHIFT);
                if (edge && (cgb + 0 >= C_SZ)) t0 = 0.f;
                if (edge && (cgb + 1 >= C_SZ)) t1 = 0.f;
                es[mt][h] += t0 + t1;
            }
        }
    #pragma unroll
    for (int m = 1; m <= 2; m <<= 1)
        #pragma unroll
        for (int mt = 0; mt < 4; mt++) {
            es[mt][0] += __shfl_xor_sync(0xffffffffu, es[mt][0], m);
            es[mt][1] += __shfl_xor_sync(0xffffffffu, es[mt][1], m);
        }

    float* rbuf = (float*)(smem + RBUF_OFF);          // [2 wm][4 wn][64 rows]
    if ((lane & 3) == 0) {
        int rl = lane >> 2;
        #pragma unroll
        for (int mt = 0; mt < 4; mt++) {
            rbuf[(wm * 4 + wn) * 64 + mt * 16 + rl]     = es[mt][0];
            rbuf[(wm * 4 + wn) * 64 + mt * 16 + 8 + rl] = es[mt][1];
        }
    }
    __syncthreads();
    if (tid < 128) {
        int wmx = tid >> 6, rl = tid & 63;
        float s = rbuf[(wmx * 4 + 0) * 64 + rl] + rbuf[(wmx * 4 + 1) * 64 + rl]
                + rbuf[(wmx * 4 + 2) * 64 + rl] + rbuf[(wmx * 4 + 3) * 64 + rl];
        atomicAdd(&g_rowsum[b0 + tid], s);            // RED.ADD, 512 addrs, low contention
    }
}

// ---------------- kernel 3: final — per-row loss + mean (1 block) ----------------
__global__ void final_kernel(const float* __restrict__ lamp, float* __restrict__ out) {
    int b = threadIdx.x;     // 512
    float lam = *lamp;

    float S0 = g_rowsum[b];
    float sv[4], svraw[4];
    int sidx[4];
    #pragma unroll
    for (int q = 0; q < 4; q++) {
        sv[q]    = g_sv[b * 4 + q];
        svraw[q] = g_svraw[b * 4 + q];
        sidx[q]  = g_sidx[b * 4 + q];
    }
    #pragma unroll
    for (int q = 0; q < 3; q++) {
        bool lastq = true;
        #pragma unroll
        for (int r = q + 1; r < 4; r++) if (sidx[r] == sidx[q]) lastq = false;
        if (lastq) S0 += __expf(sv[q] - SHIFT) - __expf(svraw[q] - SHIFT);
    }
    S0 += __expf(sv[3] - SHIFT) - __expf(svraw[3] - SHIFT);
    float lz = SHIFT + logf(S0);
    float l = lam * (0.2f * (lz - sv[0]) + 0.8f * (lz - sv[1]))
            + (1.f - lam) * (0.2f * (lz - sv[2]) + 0.8f * (lz - sv[3]));

    __shared__ float red[512];
    red[b] = l;
    __syncthreads();
    for (int st = 256; st; st >>= 1) {
        if (b < st) red[b] += red[b + st];
        __syncthreads();
    }
    if (b == 0) out[0] = red[0] / (float)B_SZ;
}

// ---------------- host launch ----------------
extern "C" void kernel_launch(void* const* d_in, const int* in_sizes, int n_in,
                              void* d_out, int out_size) {
    const float* x   = (const float*)d_in[0];
    const float* w   = (const float*)d_in[1];
    const float* lam = (const float*)d_in[2];
    const int* t1    = (const int*)d_in[3];
    const int* p1    = (const int*)d_in[4];
    const int* t2    = (const int*)d_in[5];
    const int* p2    = (const int*)d_in[6];
    float* out = (float*)d_out;

    static bool attr_set = false;
    if (!attr_set) {
        cudaFuncSetAttribute(gemm_lse_kernel,
                             cudaFuncAttributeMaxDynamicSharedMemorySize, GEMM_SMEM);
        attr_set = true;
    }

    prep_kernel<<<PREP_BLOCKS, 256>>>(w, x, t1, p1, t2, p2);
    gemm_lse_kernel<<<dim3(4, NCHB), 256, GEMM_SMEM>>>();
    final_kernel<<<1, 512>>>(lam, out);
}

// round 17
// speedup vs baseline: 1.0881x; 1.0881x over previous
#include <cuda_runtime.h>
#include <cuda_fp16.h>
#include <cstdint>

// ---------------- problem constants ----------------
#define B_SZ 512
#define D_SZ 256
#define C_SZ 100000
#define C_PAD 100096              // 782 * 128
#define NCHB 782                  // class chunks of 128
#define MARGIN 0.2f
#define SCALE  30.0f
#define SHIFT  30.0f              // fixed LSE shift: logits <= S = 30
#define WCONV_BLOCKS 6250         // 16 classes per block (2 per warp)
#define SPEC_BLOCKS  256          // 2 rows per block (8 warps = 2x4 queries)
#define PREP_BLOCKS (WCONV_BLOCKS + B_SZ + SPEC_BLOCKS)

// GEMM smem: 4 stages x (A 8KB + B 8KB) = 64KB, + 1KB reduce buffer
#define STAGE_BYTES 16384
#define RBUF_OFF    65536
#define GEMM_SMEM   (65536 + 1024)

// ---------------- device scratch (no runtime alloc) ----------------
__device__ __align__(16) __half g_wh[(size_t)C_PAD * D_SZ];  // l2norm(W) fp16; pad rows zero
__device__ __align__(16) __half g_xh[B_SZ * D_SZ];           // S * l2norm(x) fp16
__device__ float g_rowsum[B_SZ];                // per-row sum of exp(v - SHIFT), atomic
__device__ float g_sv[B_SZ * 4];                // post-scatter special values
__device__ float g_svraw[B_SZ * 4];             // raw S*cos at special indices (quantized ops)
__device__ int   g_sidx[B_SZ * 4];              // special indices

// ---------------- PTX helpers ----------------
__device__ __forceinline__ uint32_t smem_u32(const void* p) {
    uint32_t a;
    asm("{ .reg .u64 t; cvta.to.shared.u64 t, %1; cvt.u32.u64 %0, t; }" : "=r"(a) : "l"(p));
    return a;
}
#define CP_ASYNC16(dst, src) \
    asm volatile("cp.async.cg.shared.global [%0], [%1], 16;" :: "r"(dst), "l"(src) : "memory")
#define CP_COMMIT() asm volatile("cp.async.commit_group;" ::: "memory")
#define CP_WAIT(n)  asm volatile("cp.async.wait_group %0;" :: "n"(n) : "memory")

#define LDSM_X4(r0, r1, r2, r3, addr) \
    asm volatile("ldmatrix.sync.aligned.m8n8.x4.shared.b16 {%0,%1,%2,%3}, [%4];" \
        : "=r"(r0), "=r"(r1), "=r"(r2), "=r"(r3) : "r"(addr))

// fp16 in, fp16 accumulate: D(2x f16x2) = A(4) * B(2) + D
#define MMA_F16ACC(d0, d1, a0, a1, a2, a3, b0, b1) \
    asm volatile("mma.sync.aligned.m16n8k16.row.col.f16.f16.f16.f16 " \
        "{%0,%1}, {%2,%3,%4,%5}, {%6,%7}, {%0,%1};" \
        : "+r"(d0), "+r"(d1) \
        : "r"(a0), "r"(a1), "r"(a2), "r"(a3), "r"(b0), "r"(b1))

__device__ __forceinline__ float q16(float v) {   // quantize to fp16, back to fp32
    return __half2float(__float2half_rn(v));
}

// ---------------- kernel 1: fused prep (W conv | x conv | specials) ----------------
__global__ void prep_kernel(const float* __restrict__ w, const float* __restrict__ x,
                            const int* __restrict__ t1, const int* __restrict__ p1,
                            const int* __restrict__ t2, const int* __restrict__ p2) {
    int bid = blockIdx.x;
    if (bid < WCONV_BLOCKS) {
        // ---- W rows -> l2norm fp16, 16 classes/block, 2 per warp ----
        int cls0 = bid * 16 + (threadIdx.x >> 5) * 2;
        int lane = threadIdx.x & 31;
        const float4* w0r = (const float4*)(w + (size_t)cls0 * D_SZ);
        const float4* w1r = (const float4*)(w + (size_t)(cls0 + 1) * D_SZ);
        float4 a0 = w0r[lane], a1 = w0r[lane + 32];
        float4 b0 = w1r[lane], b1 = w1r[lane + 32];
        float sa = a0.x*a0.x + a0.y*a0.y + a0.z*a0.z + a0.w*a0.w
                 + a1.x*a1.x + a1.y*a1.y + a1.z*a1.z + a1.w*a1.w;
        float sb = b0.x*b0.x + b0.y*b0.y + b0.z*b0.z + b0.w*b0.w
                 + b1.x*b1.x + b1.y*b1.y + b1.z*b1.z + b1.w*b1.w;
        #pragma unroll
        for (int m = 16; m; m >>= 1) {
            sa += __shfl_xor_sync(0xffffffffu, sa, m);
            sb += __shfl_xor_sync(0xffffffffu, sb, m);
        }
        float ia = 1.0f / fmaxf(sqrtf(sa), 1e-12f);
        float ib = 1.0f / fmaxf(sqrtf(sb), 1e-12f);
        __half2* o0 = (__half2*)(g_wh + (size_t)cls0 * D_SZ);
        __half2* o1 = (__half2*)(g_wh + (size_t)(cls0 + 1) * D_SZ);
        o0[2*lane]        = __floats2half2_rn(a0.x * ia, a0.y * ia);
        o0[2*lane + 1]    = __floats2half2_rn(a0.z * ia, a0.w * ia);
        o0[64 + 2*lane]   = __floats2half2_rn(a1.x * ia, a1.y * ia);
        o0[64 + 2*lane+1] = __floats2half2_rn(a1.z * ia, a1.w * ia);
        o1[2*lane]        = __floats2half2_rn(b0.x * ib, b0.y * ib);
        o1[2*lane + 1]    = __floats2half2_rn(b0.z * ib, b0.w * ib);
        o1[64 + 2*lane]   = __floats2half2_rn(b1.x * ib, b1.y * ib);
        o1[64 + 2*lane+1] = __floats2half2_rn(b1.z * ib, b1.w * ib);
    } else if (bid < WCONV_BLOCKS + B_SZ) {
        // ---- x row -> S * l2norm(x) fp16 ----
        int b = bid - WCONV_BLOCKS, t = threadIdx.x;   // 256 threads
        if (t == 0) g_rowsum[b] = 0.f;                 // per-call reset (graph-replay safe)
        float v = x[b * D_SZ + t];
        float s = v * v;
        #pragma unroll
        for (int m = 16; m; m >>= 1) s += __shfl_xor_sync(0xffffffffu, s, m);
        __shared__ float ws[8];
        if ((t & 31) == 0) ws[t >> 5] = s;
        __syncthreads();
        __shared__ float inv;
        if (t == 0) {
            float tot = 0.f;
            #pragma unroll
            for (int i = 0; i < 8; i++) tot += ws[i];
            inv = 1.0f / fmaxf(sqrtf(tot), 1e-12f);
        }
        __syncthreads();
        g_xh[b * D_SZ + t] = __float2half_rn(SCALE * v * inv);
    } else {
        // ---- specials: 8 warps = 2 rows x 4 queries; inline quantization ----
        int wid = threadIdx.x >> 5, lane = threadIdx.x & 31;
        int b = (bid - (WCONV_BLOCKS + B_SZ)) * 2 + (wid >> 2);
        int q = wid & 3;
        int i0 = t1[b], i1 = p1[b], i2 = t2[b], i3 = p2[b];
        int qi = (q == 0) ? i0 : (q == 1) ? i1 : (q == 2) ? i2 : i3;

        const float4* xr = (const float4*)(x + (size_t)b * D_SZ);
        const float4* wr = (const float4*)(w + (size_t)qi * D_SZ);
        float4 x0 = xr[2*lane], x1 = xr[2*lane+1];
        float4 w0 = wr[2*lane], w1 = wr[2*lane+1];
        float sx = x0.x*x0.x + x0.y*x0.y + x0.z*x0.z + x0.w*x0.w
                 + x1.x*x1.x + x1.y*x1.y + x1.z*x1.z + x1.w*x1.w;
        float sw = w0.x*w0.x + w0.y*w0.y + w0.z*w0.z + w0.w*w0.w
                 + w1.x*w1.x + w1.y*w1.y + w1.z*w1.z + w1.w*w1.w;
        #pragma unroll
        for (int m = 16; m; m >>= 1) {
            sx += __shfl_xor_sync(0xffffffffu, sx, m);
            sw += __shfl_xor_sync(0xffffffffu, sw, m);
        }
        float ix = 1.0f / fmaxf(sqrtf(sx), 1e-12f);
        float iw = 1.0f / fmaxf(sqrtf(sw), 1e-12f);
        float xq[8] = {x0.x, x0.y, x0.z, x0.w, x1.x, x1.y, x1.z, x1.w};
        float wq[8] = {w0.x, w0.y, w0.z, w0.w, w1.x, w1.y, w1.z, w1.w};
        float s = 0.f;
        #pragma unroll
        for (int i = 0; i < 8; i++)
            s += q16(SCALE * xq[i] * ix) * q16(wq[i] * iw);
        #pragma unroll
        for (int m = 16; m; m >>= 1) s += __shfl_xor_sync(0xffffffffu, s, m);
        if (lane == 0) {
            float raw = s;                               // ~= what the GEMM sums
            float val = raw;
            if (qi == i0) val = raw - SCALE * MARGIN;    // pre-scale scatter
            if (qi == i1) val = raw / SCALE - MARGIN;    // post-scale scatters
            if (qi == i2) val = raw / SCALE - MARGIN;
            if (qi == i3) val = raw / SCALE - MARGIN;    // last write wins
            g_svraw[b * 4 + q] = raw;
            g_sv[b * 4 + q] = val;
            g_sidx[b * 4 + q] = qi;
        }
    }
}

// ---------------- kernel 2: fp16 HMMA GEMM, 64x64 warp tiles + frag double-buffer ----------------
// grid (4, 782). 128 threads = 4 warps (2m x 2n); 3 CTAs/SM.
__global__ void __launch_bounds__(128, 3)
gemm_lse_kernel() {
    extern __shared__ __align__(1024) char smem[];
    const uint32_t sb = smem_u32(smem);
    const int tid = threadIdx.x, lane = tid & 31, wid = tid >> 5;
    const int wm = wid >> 1, wn = wid & 1;            // warp grid 2 x 2
    const int chunk = blockIdx.y, c0 = chunk * 128, b0 = blockIdx.x * 128;

    // ---- cp.async producer: 4 A-chunks + 4 B-chunks of 16B per thread ----
    uint32_t swz[4];
    const __half *gA[4], *gB[4];
    #pragma unroll
    for (int i = 0; i < 4; i++) {
        int f = tid + 128 * i;                // 16B chunk id in 128x32 tile
        int row = f >> 2, c16 = f & 3;
        swz[i] = (uint32_t)row * 64 + ((uint32_t)(c16 ^ ((row >> 1) & 3)) << 4);
        gA[i] = g_xh + (size_t)(b0 + row) * D_SZ + c16 * 8;
        gB[i] = g_wh + (size_t)(c0 + row) * D_SZ + c16 * 8;
    }

    auto load_stage = [&](int kt) {
        uint32_t abase = sb + (kt & 3) * STAGE_BYTES;
        uint32_t bbase = abase + 8192;
        #pragma unroll
        for (int i = 0; i < 4; i++) CP_ASYNC16(abase + swz[i], gA[i] + kt * 32);
        #pragma unroll
        for (int i = 0; i < 4; i++) CP_ASYNC16(bbase + swz[i], gB[i] + kt * 32);
        CP_COMMIT();
    };

    // ---- ldmatrix consumer indexing ----
    const int rA = wm * 64 + (lane & 15);
    const uint32_t aoff = (uint32_t)rA * 64;
    const int saN = (rA >> 1) & 3;
    const int cA = lane >> 4;
    const int rB = wn * 64 + ((lane >> 4) << 3) + (lane & 7);
    const uint32_t boff = (uint32_t)rB * 64;
    const int sbN = (rB >> 1) & 3;
    const int cB = (lane >> 3) & 1;

    uint32_t acc[4][8][2];                 // f16x2 accumulators, 64 regs
    #pragma unroll
    for (int i = 0; i < 4; i++)
        #pragma unroll
        for (int j = 0; j < 8; j++) { acc[i][j][0] = 0u; acc[i][j][1] = 0u; }

    uint32_t fa0[4][4], fb0[4][4], fa1[4][4], fb1[4][4];   // double-buffered fragments

    auto ldsm_frags = [&](int st, int s, uint32_t fa[4][4], uint32_t fb[4][4]) {
        uint32_t aBase = sb + st * STAGE_BYTES;
        uint32_t bBase = aBase + 8192;
        #pragma unroll
        for (int mt = 0; mt < 4; mt++) {
            uint32_t ad = aBase + aoff + mt * 1024 +
                          ((uint32_t)((s * 2 + cA) ^ saN) << 4);
            LDSM_X4(fa[mt][0], fa[mt][1], fa[mt][2], fa[mt][3], ad);
        }
        #pragma unroll
        for (int jp = 0; jp < 4; jp++) {
            uint32_t bd = bBase + boff + jp * 1024 +
                          ((uint32_t)((s * 2 + cB) ^ sbN) << 4);
            LDSM_X4(fb[jp][0], fb[jp][1], fb[jp][2], fb[jp][3], bd);
        }
    };

    auto mma_all = [&](uint32_t fa[4][4], uint32_t fb[4][4]) {
        #pragma unroll
        for (int mt = 0; mt < 4; mt++)
            #pragma unroll
            for (int nt = 0; nt < 8; nt++) {
                int jp = nt >> 1, hb = (nt & 1) * 2;
                MMA_F16ACC(acc[mt][nt][0], acc[mt][nt][1],
                           fa[mt][0], fa[mt][1], fa[mt][2], fa[mt][3],
                           fb[jp][hb], fb[jp][hb + 1]);
            }
    };

    // ---- pipeline: 8 K-stages, 4 smem buffers, register frag double-buffer ----
    load_stage(0); load_stage(1); load_stage(2);
    CP_WAIT(2); __syncthreads();
    ldsm_frags(0, 0, fa0, fb0);
    #pragma unroll 1
    for (int kt = 0; kt < 8; kt++) {
        ldsm_frags(kt & 3, 1, fa1, fb1);    // k-step s=1 of current stage
        mma_all(fa0, fb0);                  // overlaps with the LDSMs above
        if (kt < 5) load_stage(kt + 3);
        if (kt < 7) {
            if (kt < 5)      CP_WAIT(2);
            else             CP_WAIT(1);    // kt==5; kt==6 handled below
            if (kt == 6)     CP_WAIT(0);
            __syncthreads();
            ldsm_frags((kt + 1) & 3, 0, fa0, fb0);   // next stage s=0
        }
        mma_all(fa1, fb1);                  // overlaps with next-stage LDSMs
    }

    // ---- epilogue: per-row sum of exp(v - SHIFT), one atomic per row ----
    const bool edge = (c0 + 128 > C_SZ);
    float es[4][2];
    #pragma unroll
    for (int mt = 0; mt < 4; mt++) { es[mt][0] = 0.f; es[mt][1] = 0.f; }
    #pragma unroll
    for (int mt = 0; mt < 4; mt++)
        #pragma unroll
        for (int nt = 0; nt < 8; nt++) {
            int cgb = c0 + wn * 64 + nt * 8 + (lane & 3) * 2;
            #pragma unroll
            for (int h = 0; h < 2; h++) {
                float2 v = __half22float2(*(__half2*)&acc[mt][nt][h]);
                float t0 = __expf(v.x - SHIFT);
                float t1 = __expf(v.y - SHIFT);
                if (edge && (cgb + 0 >= C_SZ)) t0 = 0.f;
                if (edge && (cgb + 1 >= C_SZ)) t1 = 0.f;
                es[mt][h] += t0 + t1;
            }
        }
    #pragma unroll
    for (int m = 1; m <= 2; m <<= 1)
        #pragma unroll
        for (int mt = 0; mt < 4; mt++) {
            es[mt][0] += __shfl_xor_sync(0xffffffffu, es[mt][0], m);
            es[mt][1] += __shfl_xor_sync(0xffffffffu, es[mt][1], m);
        }

    float* rbuf = (float*)(smem + RBUF_OFF);          // [2 wm][2 wn][64 rows]
    if ((lane & 3) == 0) {
        int rl = lane >> 2;
        #pragma unroll
        for (int mt = 0; mt < 4; mt++) {
            rbuf[(wm * 2 + wn) * 64 + mt * 16 + rl]     = es[mt][0];
            rbuf[(wm * 2 + wn) * 64 + mt * 16 + 8 + rl] = es[mt][1];
        }
    }
    __syncthreads();
    {
        int wmx = tid >> 6, rl = tid & 63;
        float s = rbuf[(wmx * 2 + 0) * 64 + rl] + rbuf[(wmx * 2 + 1) * 64 + rl];
        atomicAdd(&g_rowsum[b0 + tid], s);            // RED.ADD, 512 addrs, low contention
    }
}

// ---------------- kernel 3: final — per-row loss + mean (1 block) ----------------
__global__ void final_kernel(const float* __restrict__ lamp, float* __restrict__ out) {
    int b = threadIdx.x;     // 512
    float lam = *lamp;

    float S0 = g_rowsum[b];
    float sv[4], svraw[4];
    int sidx[4];
    #pragma unroll
    for (int q = 0; q < 4; q++) {
        sv[q]    = g_sv[b * 4 + q];
        svraw[q] = g_svraw[b * 4 + q];
        sidx[q]  = g_sidx[b * 4 + q];
    }
    #pragma unroll
    for (int q = 0; q < 3; q++) {
        bool lastq = true;
        #pragma unroll
        for (int r = q + 1; r < 4; r++) if (sidx[r] == sidx[q]) lastq = false;
        if (lastq) S0 += __expf(sv[q] - SHIFT) - __expf(svraw[q] - SHIFT);
    }
    S0 += __expf(sv[3] - SHIFT) - __expf(svraw[3] - SHIFT);
    float lz = SHIFT + logf(S0);
    float l = lam * (0.2f * (lz - sv[0]) + 0.8f * (lz - sv[1]))
            + (1.f - lam) * (0.2f * (lz - sv[2]) + 0.8f * (lz - sv[3]));

    __shared__ float red[512];
    red[b] = l;
    __syncthreads();
    for (int st = 256; st; st >>= 1) {
        if (b < st) red[b] += red[b + st];
        __syncthreads();
    }
    if (b == 0) out[0] = red[0] / (float)B_SZ;
}

// ---------------- host launch ----------------
extern "C" void kernel_launch(void* const* d_in, const int* in_sizes, int n_in,
                              void* d_out, int out_size) {
    const float* x   = (const float*)d_in[0];
    const float* w   = (const float*)d_in[1];
    const float* lam = (const float*)d_in[2];
    const int* t1    = (const int*)d_in[3];
    const int* p1    = (const int*)d_in[4];
    const int* t2    = (const int*)d_in[5];
    const int* p2    = (const int*)d_in[6];
    float* out = (float*)d_out;

    static bool attr_set = false;
    if (!attr_set) {
        cudaFuncSetAttribute(gemm_lse_kernel,
                             cudaFuncAttributeMaxDynamicSharedMemorySize, GEMM_SMEM);
        attr_set = true;
    }

    prep_kernel<<<PREP_BLOCKS, 256>>>(w, x, t1, p1, t2, p2);
    gemm_lse_kernel<<<dim3(4, NCHB), 128, GEMM_SMEM>>>();
    final_kernel<<<1, 512>>>(lam, out);
}